// round 3
// baseline (speedup 1.0000x reference)
#include <cuda_runtime.h>
#include <cstdint>
#include <cstddef>

#define NN 8192
#define KC 16
#define DD 64
#define JCHUNK 512
#define NCHUNK (NN / JCHUNK)      // 16
#define ROWS_PER_WARP 4
#define WARPS_PER_BLK 8
#define ROWS_PER_BLK (ROWS_PER_WARP * WARPS_PER_BLK)   // 32
#define NBLK2 (NN / ROWS_PER_BLK)                      // 256

static __device__ __align__(16) float g_piT[KC][NN];   // u transposed: [k][j]
static __device__ __align__(16) float g_v[NN * KC];    // v[i][k] row-major
static __device__ float g_partials[NBLK2];

// ------------------------------------------------------------------
// Kernel 1: distances -> softmax pi -> write piT (u) and v
// ------------------------------------------------------------------
__global__ void __launch_bounds__(64)
pi_kernel(const float* __restrict__ emb,    // (3, NN, DD)
          const float* __restrict__ comm,   // (KC, DD)
          const float* __restrict__ alpha_p) {
    __shared__ float sc[KC][DD];
    __shared__ float scn[KC];
    const int tid = threadIdx.x;
    for (int idx = tid; idx < KC * DD; idx += 64)
        sc[idx >> 6][idx & 63] = comm[idx];
    __syncthreads();
    if (tid < KC) {
        float sq = 0.f;
        #pragma unroll
        for (int d = 0; d < DD; ++d) sq = fmaf(sc[tid][d], sc[tid][d], sq);
        scn[tid] = sq;
    }
    __syncthreads();

    const int n = blockIdx.x * 64 + tid;

    const float LOR_MIN = (float)(1.0 + 1e-7);
    const float CLIP_LO = (float)(-1.0 + 1e-7);
    const float CLIP_HI = (float)(1.0 - 1e-7);

    float dist2[KC];
    float4 xr[16];

    // ---- manifold 0: Euclidean ----
    {
        const float4* xp = reinterpret_cast<const float4*>(emb) + (size_t)n * 16;
        #pragma unroll
        for (int q = 0; q < 16; ++q) xr[q] = xp[q];
        float xn2 = 0.f;
        #pragma unroll
        for (int q = 0; q < 16; ++q) {
            xn2 = fmaf(xr[q].x, xr[q].x, xn2);
            xn2 = fmaf(xr[q].y, xr[q].y, xn2);
            xn2 = fmaf(xr[q].z, xr[q].z, xn2);
            xn2 = fmaf(xr[q].w, xr[q].w, xn2);
        }
        #pragma unroll
        for (int k = 0; k < KC; ++k) {
            float dot = 0.f;
            #pragma unroll
            for (int q = 0; q < 16; ++q) {
                dot = fmaf(xr[q].x, sc[k][4 * q + 0], dot);
                dot = fmaf(xr[q].y, sc[k][4 * q + 1], dot);
                dot = fmaf(xr[q].z, sc[k][4 * q + 2], dot);
                dot = fmaf(xr[q].w, sc[k][4 * q + 3], dot);
            }
            dist2[k] = fmaxf(xn2 - 2.f * dot + scn[k], 0.f);
        }
    }
    // ---- manifold 1: Lorentz (curvature -1, kk = 1) ----
    {
        const float4* xp = reinterpret_cast<const float4*>(emb) + (size_t)(NN + n) * 16;
        #pragma unroll
        for (int q = 0; q < 16; ++q) xr[q] = xp[q];
        const float x0 = xr[0].x;
        #pragma unroll
        for (int k = 0; k < KC; ++k) {
            float dot = 0.f;
            #pragma unroll
            for (int q = 0; q < 16; ++q) {
                dot = fmaf(xr[q].x, sc[k][4 * q + 0], dot);
                dot = fmaf(xr[q].y, sc[k][4 * q + 1], dot);
                dot = fmaf(xr[q].z, sc[k][4 * q + 2], dot);
                dot = fmaf(xr[q].w, sc[k][4 * q + 3], dot);
            }
            float lip = dot - 2.f * x0 * sc[k][0];
            float arg = fmaxf(-lip, LOR_MIN);
            float dl  = acoshf(arg);
            dist2[k]  = fmaf(dl, dl, dist2[k]);
        }
    }
    // ---- manifold 2: Sphere ----
    {
        const float4* xp = reinterpret_cast<const float4*>(emb) + (size_t)(2 * NN + n) * 16;
        #pragma unroll
        for (int q = 0; q < 16; ++q) xr[q] = xp[q];
        #pragma unroll
        for (int k = 0; k < KC; ++k) {
            float dot = 0.f;
            #pragma unroll
            for (int q = 0; q < 16; ++q) {
                dot = fmaf(xr[q].x, sc[k][4 * q + 0], dot);
                dot = fmaf(xr[q].y, sc[k][4 * q + 1], dot);
                dot = fmaf(xr[q].z, sc[k][4 * q + 2], dot);
                dot = fmaf(xr[q].w, sc[k][4 * q + 3], dot);
            }
            float cosv = fminf(fmaxf(dot, CLIP_LO), CLIP_HI);
            float ds   = acosf(cosv);
            dist2[k]   = fmaf(ds, ds, dist2[k]);
        }
    }

    // dist_norm then softmax over KC
    float dn[KC];
    float m = -1e30f;
    #pragma unroll
    for (int k = 0; k < KC; ++k) { dn[k] = sqrtf(dist2[k]); m = fmaxf(m, dn[k]); }
    float e[KC];
    float esum = 0.f;
    #pragma unroll
    for (int k = 0; k < KC; ++k) { e[k] = expf(dn[k] - m); esum += e[k]; }
    const float inv = 1.f / esum;
    float pi[KC];
    float s = 0.f;
    #pragma unroll
    for (int k = 0; k < KC; ++k) { pi[k] = e[k] * inv; s += pi[k]; }

    const float a  = alpha_p[0];
    const float c1 = a * (1.f / ((float)KC * (float)NN));            // alpha/(K*N)
    const float c2 = 1.f / ((float)KC * (float)KC * (float)NN);      // 1/(K*K*N)

    #pragma unroll
    for (int k = 0; k < KC; ++k) g_piT[k][n] = pi[k];
    #pragma unroll
    for (int g = 0; g < 4; ++g) {
        float4 vv;
        vv.x = fmaf(c1, pi[4 * g + 0], -c2 * s);
        vv.y = fmaf(c1, pi[4 * g + 1], -c2 * s);
        vv.z = fmaf(c1, pi[4 * g + 2], -c2 * s);
        vv.w = fmaf(c1, pi[4 * g + 3], -c2 * s);
        *reinterpret_cast<float4*>(g_v + (size_t)n * KC + 4 * g) = vv;
    }
}

// ------------------------------------------------------------------
// Kernel 2: partial[b] = sum_{i in block rows} sum_j r_ij * (v_i . u_j)
// Each warp owns 4 rows; each lane covers 4 consecutive j per step.
// ------------------------------------------------------------------
__global__ void __launch_bounds__(256)
bilinear_kernel(const float* __restrict__ R) {
    __shared__ __align__(16) float su[KC][JCHUNK];
    __shared__ float red[256];

    const int tid  = threadIdx.x;
    const int warp = tid >> 5;
    const int lane = tid & 31;
    const int row0 = blockIdx.x * ROWS_PER_BLK + warp * ROWS_PER_WARP;

    // v for this warp's 4 rows -> registers
    float v[ROWS_PER_WARP][KC];
    #pragma unroll
    for (int i = 0; i < ROWS_PER_WARP; ++i) {
        const float4* vp = reinterpret_cast<const float4*>(g_v + (size_t)(row0 + i) * KC);
        #pragma unroll
        for (int q = 0; q < 4; ++q) {
            float4 t = vp[q];
            v[i][4 * q + 0] = t.x;
            v[i][4 * q + 1] = t.y;
            v[i][4 * q + 2] = t.z;
            v[i][4 * q + 3] = t.w;
        }
    }

    const float* r0p = R + (size_t)(row0 + 0) * NN;
    const float* r1p = R + (size_t)(row0 + 1) * NN;
    const float* r2p = R + (size_t)(row0 + 2) * NN;
    const float* r3p = R + (size_t)(row0 + 3) * NN;

    float acc = 0.f;

    for (int jc = 0; jc < NCHUNK; ++jc) {
        __syncthreads();
        // load su tile: 16 x 512 floats = 2048 float4, 256 threads -> 8 each
        {
            const float4* src = reinterpret_cast<const float4*>(&g_piT[0][0]);
            float4* dst = reinterpret_cast<float4*>(&su[0][0]);
            #pragma unroll
            for (int r = 0; r < 8; ++r) {
                int idx = r * 256 + tid;          // 0..2047
                int k   = idx >> 7;               // / 128
                int jj  = idx & 127;
                dst[idx] = src[(size_t)k * (NN / 4) + (size_t)jc * (JCHUNK / 4) + jj];
            }
        }
        __syncthreads();

        const float4* su4 = reinterpret_cast<const float4*>(&su[0][0]); // [k*128 + j4]

        #pragma unroll
        for (int it = 0; it < 4; ++it) {
            const int j4 = it * 32 + lane;                      // float4 index in chunk
            const size_t joff = (size_t)jc * JCHUNK + (size_t)j4 * 4;

            float4 r0 = *reinterpret_cast<const float4*>(r0p + joff);
            float4 r1 = *reinterpret_cast<const float4*>(r1p + joff);
            float4 r2 = *reinterpret_cast<const float4*>(r2p + joff);
            float4 r3 = *reinterpret_cast<const float4*>(r3p + joff);

            float4 s0 = make_float4(0.f, 0.f, 0.f, 0.f);
            float4 s1 = make_float4(0.f, 0.f, 0.f, 0.f);
            float4 s2 = make_float4(0.f, 0.f, 0.f, 0.f);
            float4 s3 = make_float4(0.f, 0.f, 0.f, 0.f);

            #pragma unroll
            for (int k = 0; k < KC; ++k) {
                float4 u = su4[k * (JCHUNK / 4) + j4];
                s0.x = fmaf(u.x, v[0][k], s0.x);
                s0.y = fmaf(u.y, v[0][k], s0.y);
                s0.z = fmaf(u.z, v[0][k], s0.z);
                s0.w = fmaf(u.w, v[0][k], s0.w);
                s1.x = fmaf(u.x, v[1][k], s1.x);
                s1.y = fmaf(u.y, v[1][k], s1.y);
                s1.z = fmaf(u.z, v[1][k], s1.z);
                s1.w = fmaf(u.w, v[1][k], s1.w);
                s2.x = fmaf(u.x, v[2][k], s2.x);
                s2.y = fmaf(u.y, v[2][k], s2.y);
                s2.z = fmaf(u.z, v[2][k], s2.z);
                s2.w = fmaf(u.w, v[2][k], s2.w);
                s3.x = fmaf(u.x, v[3][k], s3.x);
                s3.y = fmaf(u.y, v[3][k], s3.y);
                s3.z = fmaf(u.z, v[3][k], s3.z);
                s3.w = fmaf(u.w, v[3][k], s3.w);
            }

            acc = fmaf(r0.x, s0.x, acc);
            acc = fmaf(r0.y, s0.y, acc);
            acc = fmaf(r0.z, s0.z, acc);
            acc = fmaf(r0.w, s0.w, acc);
            acc = fmaf(r1.x, s1.x, acc);
            acc = fmaf(r1.y, s1.y, acc);
            acc = fmaf(r1.z, s1.z, acc);
            acc = fmaf(r1.w, s1.w, acc);
            acc = fmaf(r2.x, s2.x, acc);
            acc = fmaf(r2.y, s2.y, acc);
            acc = fmaf(r2.z, s2.z, acc);
            acc = fmaf(r2.w, s2.w, acc);
            acc = fmaf(r3.x, s3.x, acc);
            acc = fmaf(r3.y, s3.y, acc);
            acc = fmaf(r3.z, s3.z, acc);
            acc = fmaf(r3.w, s3.w, acc);
        }
    }

    // block reduction (fixed tree -> deterministic)
    red[tid] = acc;
    __syncthreads();
    #pragma unroll
    for (int off = 128; off >= 1; off >>= 1) {
        if (tid < off) red[tid] += red[tid + off];
        __syncthreads();
    }
    if (tid == 0) g_partials[blockIdx.x] = red[0];
}

// ------------------------------------------------------------------
// Kernel 3: finalize — sum partials, write scalar
// ------------------------------------------------------------------
__global__ void __launch_bounds__(256)
finalize_kernel(float* __restrict__ out) {
    __shared__ float red[256];
    const int tid = threadIdx.x;
    float a = (tid < NBLK2) ? g_partials[tid] : 0.f;
    red[tid] = a;
    __syncthreads();
    #pragma unroll
    for (int off = 128; off >= 1; off >>= 1) {
        if (tid < off) red[tid] += red[tid + off];
        __syncthreads();
    }
    if (tid == 0) out[0] = red[0];
}

// ------------------------------------------------------------------
extern "C" void kernel_launch(void* const* d_in, const int* in_sizes, int n_in,
                              void* d_out, int out_size) {
    const float* emb   = (const float*)d_in[0];   // (3, 8192, 64)
    const float* comm  = (const float*)d_in[1];   // (16, 64)
    const float* ricci = (const float*)d_in[2];   // (8192, 8192)
    const float* alpha = (const float*)d_in[3];   // scalar
    float* out = (float*)d_out;

    pi_kernel<<<NN / 64, 64>>>(emb, comm, alpha);
    bilinear_kernel<<<NBLK2, 256>>>(ricci);
    finalize_kernel<<<1, 256>>>(out);
}

// round 4
// speedup vs baseline: 2.6102x; 2.6102x over previous
#include <cuda_runtime.h>
#include <cstdint>
#include <cstddef>

#define NN 8192
#define KC 16
#define DD 64

// bilinear tiling
#define JQ 4                       // j-quarters
#define JITEM (NN / JQ)            // 2048 floats of j per block
#define JCHUNK 512
#define NCHUNK (JITEM / JCHUNK)    // 4
#define ROWS_PER_WARP 4
#define WARPS_PER_BLK 8
#define ROWS_PER_BLK (ROWS_PER_WARP * WARPS_PER_BLK)   // 32
#define NROWGRP (NN / ROWS_PER_BLK)                    // 256
#define NBLK2 (NROWGRP * JQ)                           // 1024
#define TILE_FLOATS (KC * JCHUNK)                      // 8192 floats = 32KB

static __device__ __align__(16) float g_piT[KC][NN];   // u transposed: [k][j]
static __device__ __align__(16) float g_v[NN * KC];    // v[i][k] row-major
static __device__ float g_partials[NBLK2];

// ------------------------------------------------------------------
// helpers
// ------------------------------------------------------------------
__device__ __forceinline__ unsigned long long pack2(float x, float y) {
    unsigned long long r;
    asm("mov.b64 %0, {%1, %2};" : "=l"(r) : "f"(x), "f"(y));
    return r;
}
__device__ __forceinline__ void unpack2(unsigned long long p, float& x, float& y) {
    asm("mov.b64 {%0, %1}, %2;" : "=f"(x), "=f"(y) : "l"(p));
}
__device__ __forceinline__ void fma2(unsigned long long& d, unsigned long long a,
                                     unsigned long long b) {
    asm("fma.rn.f32x2 %0, %1, %2, %0;" : "+l"(d) : "l"(a), "l"(b));
}
__device__ __forceinline__ void cp16(void* dst_smem, const void* src_gmem) {
    uint32_t d = (uint32_t)__cvta_generic_to_shared(dst_smem);
    asm volatile("cp.async.cg.shared.global [%0], [%1], 16;" :: "r"(d), "l"(src_gmem));
}

// ------------------------------------------------------------------
// Kernel 1: distances -> softmax pi -> write piT (u) and v
// layout: 256 threads = 16 nodes x 16 communities, softmax via 16-lane shuffles
// ------------------------------------------------------------------
__global__ void __launch_bounds__(256)
pi_kernel(const float* __restrict__ emb,    // (3, NN, DD)
          const float* __restrict__ comm,   // (KC, DD)
          const float* __restrict__ alpha_p) {
    const int tid  = threadIdx.x;
    const int k    = tid & 15;
    const int nloc = tid >> 4;
    const int n    = blockIdx.x * 16 + nloc;

    const float LOR_MIN = (float)(1.0 + 1e-7);
    const float CLIP_LO = (float)(-1.0 + 1e-7);
    const float CLIP_HI = (float)(1.0 - 1e-7);

    // community row for this thread's k
    float4 c4[16];
    {
        const float4* cp = reinterpret_cast<const float4*>(comm) + (size_t)k * 16;
        #pragma unroll
        for (int q = 0; q < 16; ++q) c4[q] = cp[q];
    }
    float cn = 0.f;
    #pragma unroll
    for (int q = 0; q < 16; ++q) {
        cn = fmaf(c4[q].x, c4[q].x, cn);
        cn = fmaf(c4[q].y, c4[q].y, cn);
        cn = fmaf(c4[q].z, c4[q].z, cn);
        cn = fmaf(c4[q].w, c4[q].w, cn);
    }

    float dist2;

    // ---- manifold 0: Euclidean ----
    {
        const float4* xp = reinterpret_cast<const float4*>(emb) + (size_t)n * 16;
        float dot = 0.f, xn2 = 0.f;
        #pragma unroll
        for (int q = 0; q < 16; ++q) {
            float4 x = xp[q];
            dot = fmaf(x.x, c4[q].x, dot);
            dot = fmaf(x.y, c4[q].y, dot);
            dot = fmaf(x.z, c4[q].z, dot);
            dot = fmaf(x.w, c4[q].w, dot);
            xn2 = fmaf(x.x, x.x, xn2);
            xn2 = fmaf(x.y, x.y, xn2);
            xn2 = fmaf(x.z, x.z, xn2);
            xn2 = fmaf(x.w, x.w, xn2);
        }
        dist2 = fmaxf(xn2 - 2.f * dot + cn, 0.f);
    }
    // ---- manifold 1: Lorentz (curvature -1, kk = 1) ----
    {
        const float4* xp = reinterpret_cast<const float4*>(emb) + (size_t)(NN + n) * 16;
        float dot = 0.f;
        float x0 = xp[0].x;
        #pragma unroll
        for (int q = 0; q < 16; ++q) {
            float4 x = xp[q];
            dot = fmaf(x.x, c4[q].x, dot);
            dot = fmaf(x.y, c4[q].y, dot);
            dot = fmaf(x.z, c4[q].z, dot);
            dot = fmaf(x.w, c4[q].w, dot);
        }
        float lip = dot - 2.f * x0 * c4[0].x;
        float arg = fmaxf(-lip, LOR_MIN);
        float dl  = acoshf(arg);
        dist2 = fmaf(dl, dl, dist2);
    }
    // ---- manifold 2: Sphere ----
    {
        const float4* xp = reinterpret_cast<const float4*>(emb) + (size_t)(2 * NN + n) * 16;
        float dot = 0.f;
        #pragma unroll
        for (int q = 0; q < 16; ++q) {
            float4 x = xp[q];
            dot = fmaf(x.x, c4[q].x, dot);
            dot = fmaf(x.y, c4[q].y, dot);
            dot = fmaf(x.z, c4[q].z, dot);
            dot = fmaf(x.w, c4[q].w, dot);
        }
        float cosv = fminf(fmaxf(dot, CLIP_LO), CLIP_HI);
        float ds   = acosf(cosv);
        dist2 = fmaf(ds, ds, dist2);
    }

    const float dn = sqrtf(dist2);

    // softmax across the 16 lanes that share this node
    float m = dn;
    #pragma unroll
    for (int off = 8; off >= 1; off >>= 1)
        m = fmaxf(m, __shfl_xor_sync(0xffffffffu, m, off, 16));
    float e = expf(dn - m);
    float es = e;
    #pragma unroll
    for (int off = 8; off >= 1; off >>= 1)
        es += __shfl_xor_sync(0xffffffffu, es, off, 16);
    const float pi = e / es;
    float s = pi;
    #pragma unroll
    for (int off = 8; off >= 1; off >>= 1)
        s += __shfl_xor_sync(0xffffffffu, s, off, 16);

    const float a  = alpha_p[0];
    const float c1 = a * (1.f / ((float)KC * (float)NN));        // alpha/(K*N)
    const float c2 = 1.f / ((float)KC * (float)KC * (float)NN);  // 1/(K*K*N)

    g_piT[k][n] = pi;
    g_v[(size_t)n * KC + k] = fmaf(c1, pi, -c2 * s);
}

// ------------------------------------------------------------------
// Kernel 2: partial = sum_{rows,j-range} r_ij * (v_i . u_j), f32x2 mainloop
// grid: NBLK2 blocks = 256 row-groups x 4 j-quarters
// smem: double-buffered u tile (2 x 16 x 512 floats = 64KB dynamic)
// ------------------------------------------------------------------
__global__ void __launch_bounds__(256, 1)
bilinear_kernel(const float* __restrict__ R) {
    extern __shared__ __align__(16) float su_dyn[];
    __shared__ float red[256];

    const int tid  = threadIdx.x;
    const int warp = tid >> 5;
    const int lane = tid & 31;
    const int rg   = blockIdx.x & (NROWGRP - 1);
    const int q    = blockIdx.x >> 8;
    const int row0 = rg * ROWS_PER_BLK + warp * ROWS_PER_WARP;
    const int jbase = q * JITEM;                 // in floats

    // v for this warp's 4 rows -> duplicated f32x2 packs
    unsigned long long vp[ROWS_PER_WARP][KC];
    #pragma unroll
    for (int i = 0; i < ROWS_PER_WARP; ++i) {
        const float4* vpp = reinterpret_cast<const float4*>(g_v + (size_t)(row0 + i) * KC);
        #pragma unroll
        for (int g = 0; g < 4; ++g) {
            float4 t = vpp[g];
            vp[i][4 * g + 0] = pack2(t.x, t.x);
            vp[i][4 * g + 1] = pack2(t.y, t.y);
            vp[i][4 * g + 2] = pack2(t.z, t.z);
            vp[i][4 * g + 3] = pack2(t.w, t.w);
        }
    }

    const ulonglong2* rp0 = reinterpret_cast<const ulonglong2*>(R + (size_t)(row0 + 0) * NN);
    const ulonglong2* rp1 = reinterpret_cast<const ulonglong2*>(R + (size_t)(row0 + 1) * NN);
    const ulonglong2* rp2 = reinterpret_cast<const ulonglong2*>(R + (size_t)(row0 + 2) * NN);
    const ulonglong2* rp3 = reinterpret_cast<const ulonglong2*>(R + (size_t)(row0 + 3) * NN);

    const float* piT_base = &g_piT[0][0];

    // tile loader: chunk cc -> buffer cc&1 via cp.async (2048 float4, 8/thread)
    auto load_tile = [&](int cc) {
        float* buf = su_dyn + (cc & 1) * TILE_FLOATS;
        const int jb = jbase + cc * JCHUNK;
        #pragma unroll
        for (int r = 0; r < 8; ++r) {
            int idx = r * 256 + tid;             // 0..2047
            int k   = idx >> 7;                  // / 128
            int jj  = idx & 127;
            cp16(buf + k * JCHUNK + jj * 4,
                 piT_base + (size_t)k * NN + jb + jj * 4);
        }
        asm volatile("cp.async.commit_group;" ::: "memory");
    };

    unsigned long long acc[ROWS_PER_WARP] = {0ull, 0ull, 0ull, 0ull};

    load_tile(0);

    for (int cc = 0; cc < NCHUNK; ++cc) {
        if (cc + 1 < NCHUNK) load_tile(cc + 1);
        if (cc + 1 < NCHUNK) {
            asm volatile("cp.async.wait_group 1;" ::: "memory");
        } else {
            asm volatile("cp.async.wait_group 0;" ::: "memory");
        }
        __syncthreads();

        const ulonglong2* su2 =
            reinterpret_cast<const ulonglong2*>(su_dyn + (cc & 1) * TILE_FLOATS);
        const int jidx_base = (jbase >> 2) + cc * (JCHUNK / 4);

        #pragma unroll
        for (int it = 0; it < 4; ++it) {
            const int j4 = it * 32 + lane;       // float4 index within chunk
            const int jidx = jidx_base + j4;     // float4 index within row

            // R loads early to cover DRAM latency during the k-loop
            ulonglong2 R0 = rp0[jidx];
            ulonglong2 R1 = rp1[jidx];
            ulonglong2 R2 = rp2[jidx];
            ulonglong2 R3 = rp3[jidx];

            unsigned long long s0a = 0, s0b = 0, s1a = 0, s1b = 0;
            unsigned long long s2a = 0, s2b = 0, s3a = 0, s3b = 0;

            #pragma unroll
            for (int k = 0; k < KC; ++k) {
                ulonglong2 u = su2[k * (JCHUNK / 4) + j4];
                fma2(s0a, u.x, vp[0][k]);
                fma2(s0b, u.y, vp[0][k]);
                fma2(s1a, u.x, vp[1][k]);
                fma2(s1b, u.y, vp[1][k]);
                fma2(s2a, u.x, vp[2][k]);
                fma2(s2b, u.y, vp[2][k]);
                fma2(s3a, u.x, vp[3][k]);
                fma2(s3b, u.y, vp[3][k]);
            }

            fma2(acc[0], R0.x, s0a);
            fma2(acc[0], R0.y, s0b);
            fma2(acc[1], R1.x, s1a);
            fma2(acc[1], R1.y, s1b);
            fma2(acc[2], R2.x, s2a);
            fma2(acc[2], R2.y, s2b);
            fma2(acc[3], R3.x, s3a);
            fma2(acc[3], R3.y, s3b);
        }
        __syncthreads();
    }

    // combine accumulator pairs (fixed order -> deterministic)
    float total = 0.f;
    #pragma unroll
    for (int i = 0; i < ROWS_PER_WARP; ++i) {
        float lo, hi;
        unpack2(acc[i], lo, hi);
        total += lo + hi;
    }

    red[tid] = total;
    __syncthreads();
    #pragma unroll
    for (int off = 128; off >= 1; off >>= 1) {
        if (tid < off) red[tid] += red[tid + off];
        __syncthreads();
    }
    if (tid == 0) g_partials[blockIdx.x] = red[0];
}

// ------------------------------------------------------------------
// Kernel 3: finalize — sum 1024 partials, write scalar
// ------------------------------------------------------------------
__global__ void __launch_bounds__(256)
finalize_kernel(float* __restrict__ out) {
    __shared__ float red[256];
    const int tid = threadIdx.x;
    float a = g_partials[tid] + g_partials[tid + 256] +
              g_partials[tid + 512] + g_partials[tid + 768];
    red[tid] = a;
    __syncthreads();
    #pragma unroll
    for (int off = 128; off >= 1; off >>= 1) {
        if (tid < off) red[tid] += red[tid + off];
        __syncthreads();
    }
    if (tid == 0) out[0] = red[0];
}

// ------------------------------------------------------------------
extern "C" void kernel_launch(void* const* d_in, const int* in_sizes, int n_in,
                              void* d_out, int out_size) {
    const float* emb   = (const float*)d_in[0];   // (3, 8192, 64)
    const float* comm  = (const float*)d_in[1];   // (16, 64)
    const float* ricci = (const float*)d_in[2];   // (8192, 8192)
    const float* alpha = (const float*)d_in[3];   // scalar
    float* out = (float*)d_out;

    static bool attr_done = false;
    if (!attr_done) {
        cudaFuncSetAttribute(bilinear_kernel,
                             cudaFuncAttributeMaxDynamicSharedMemorySize,
                             2 * TILE_FLOATS * (int)sizeof(float));
        attr_done = true;
    }

    pi_kernel<<<NN / 16, 256>>>(emb, comm, alpha);
    bilinear_kernel<<<NBLK2, 256, 2 * TILE_FLOATS * sizeof(float)>>>(ricci);
    finalize_kernel<<<1, 256>>>(out);
}